// round 7
// baseline (speedup 1.0000x reference)
#include <cuda_runtime.h>

#define NN 100000
#define NE 1000000

#define GEMM_BLOCKS ((NN + 31) / 32)      // 3125
#define NODEB_BLOCKS 1480

#define COMMIT_OFF (NN*64)
#define IDS_OFF (COMMIT_OFF+1)
#define GNN_OFF (IDS_OFF + NN*9)

// ---------------- scratch (__device__ globals; no allocation allowed) ----------------
__device__ __align__(16) float g_summed[NN*64];
__device__ __align__(16) float g_h[NN*64];
__device__ __align__(16) float g_hpre[NN*64];
__device__ __align__(16) float g_xlocal[NN*64];
__device__ int   g_srcI[NE];
__device__ int   g_dstI[NE];
__device__ int   g_csr[NE];
__device__ int   g_deg[NN];
__device__ int   g_fill[NN];
__device__ int   g_rowstart[NN + 1];
__device__ float g_cinv[NN];
__device__ float g_part[GEMM_BLOCKS * 128];   // per-block BN partials
__device__ float g_cpart[3 * NODEB_BLOCKS];   // per-block commit partials
__device__ float g_bn[128];                   // [0:64) scale, [64:128) shift
__device__ int   g_is64;

// ---------------- zero / init ----------------
__global__ void k_zero_init() {
    int i = blockIdx.x * blockDim.x + threadIdx.x;
    if (i < NN*64) g_xlocal[i] = 0.f;
    if (i < NN)  { g_deg[i] = 0; g_fill[i] = 0; }
}

// detect edge_index dtype: int64 values < 2^31 have zero hi-words at odd int32 slots
__global__ void k_detect(const int* __restrict__ ei32) {
    if (threadIdx.x == 0 && blockIdx.x == 0) {
        int orv = 0;
        for (int i = 1; i < 2048; i += 2) orv |= ei32[i];
        g_is64 = (orv == 0) ? 1 : 0;
    }
}

// one-time: indices -> int32 arrays + integer degree count (dtype-agnostic)
__global__ void k_prep(const void* __restrict__ eiv) {
    int e = blockIdx.x * blockDim.x + threadIdx.x;
    if (e < NE) {
        int s, d;
        if (g_is64) {
            const long long* ei = (const long long*)eiv;
            s = (int)ei[e];
            d = (int)ei[NE + e];
        } else {
            const int* ei = (const int*)eiv;
            s = ei[e];
            d = ei[NE + e];
        }
        g_srcI[e] = s;
        g_dstI[e] = d;
        atomicAdd(&g_deg[d], 1);
    }
}

// single-block prefix sum over degrees -> row_start
__global__ void __launch_bounds__(1024) k_scan() {
    __shared__ int ssum[1024];
    int t = threadIdx.x;
    const int per = (NN + 1023) / 1024;
    int lo = t * per;
    int hi = lo + per; if (hi > NN) hi = NN;
    int s = 0;
    for (int i = lo; i < hi; i++) s += g_deg[i];
    ssum[t] = s;
    __syncthreads();
    for (int off = 1; off < 1024; off <<= 1) {
        int v = 0;
        if (t >= off) v = ssum[t - off];
        __syncthreads();
        ssum[t] += v;
        __syncthreads();
    }
    int run = (t ? ssum[t - 1] : 0);
    for (int i = lo; i < hi; i++) {
        g_rowstart[i] = run;
        run += g_deg[i];
        g_cinv[i] = 1.f / (float)(g_deg[i] > 0 ? g_deg[i] : 1);
    }
    if (t == 1023) g_rowstart[NN] = run;
}

// counting-sort edges into CSR by destination
__global__ void k_fill() {
    int e = blockIdx.x * blockDim.x + threadIdx.x;
    if (e < NE) {
        int d = g_dstI[e];
        int pos = g_rowstart[d] + atomicAdd(&g_fill[d], 1);
        g_csr[pos] = g_srcI[e];
    }
}

// ---------------- gather: summed[n] = sum over incoming edges of h[src] -----------
__global__ void __launch_bounds__(256) k_gather(const float* __restrict__ x, int layer) {
    const float* __restrict__ h = layer ? g_h : x;
    int gw = (blockIdx.x * blockDim.x + threadIdx.x) >> 5;
    int lane = threadIdx.x & 31;
    if (gw >= NN) return;
    int beg = g_rowstart[gw], end = g_rowstart[gw + 1];
    float a0 = 0.f, a1 = 0.f;
    for (int j = beg; j < end; j++) {
        int s = g_csr[j];
        const float* row = h + (size_t)s * 64;
        a0 += row[lane];
        a1 += row[lane + 32];
    }
    g_summed[(size_t)gw * 64 + lane]      = a0;
    g_summed[(size_t)gw * 64 + lane + 32] = a1;
}

// ---------------- fused: mean@Wa+ba + h@Wr -> l2norm -> + h@Wl+bl ; BN partials ----
// 32 nodes x 64 channels per block, 256 threads, 2x4 microtile, one weight at a time.
// Static smem only, no atomics.
#define LDN 34
__global__ void __launch_bounds__(256) k_gemmA(
    const float* __restrict__ x, int layer,
    const float* __restrict__ Wa, const float* __restrict__ Wr,
    const float* __restrict__ Wl,
    const float* __restrict__ ba, const float* __restrict__ bl)
{
    const float* __restrict__ hin = layer ? g_h : x;
    __shared__ float sW[4096];        // one 64x64 weight
    __shared__ float sA[64 * LDN];    // meanT [k][n]
    __shared__ float sB[64 * LDN];    // hT    [k][n]
    __shared__ float sRed[8 * 128];   // per-warp stat partials

    int tid = threadIdx.x;
    int node0 = blockIdx.x * 32;

    // load tiles (transposed) + Wa
    for (int i = tid; i < 512; i += 256) {
        int n = i >> 4, kc = i & 15;
        int node = node0 + n;
        float4 mv = make_float4(0.f, 0.f, 0.f, 0.f), hv = mv;
        if (node < NN) {
            float ci = g_cinv[node];
            float4 s4 = *(const float4*)(g_summed + (size_t)node * 64 + kc * 4);
            mv = make_float4(s4.x * ci, s4.y * ci, s4.z * ci, s4.w * ci);
            hv = *(const float4*)(hin + (size_t)node * 64 + kc * 4);
        }
        int kb = kc * 4;
        sA[(kb+0)*LDN+n] = mv.x; sA[(kb+1)*LDN+n] = mv.y;
        sA[(kb+2)*LDN+n] = mv.z; sA[(kb+3)*LDN+n] = mv.w;
        sB[(kb+0)*LDN+n] = hv.x; sB[(kb+1)*LDN+n] = hv.y;
        sB[(kb+2)*LDN+n] = hv.z; sB[(kb+3)*LDN+n] = hv.w;
    }
    for (int i = tid; i < 1024; i += 256) ((float4*)sW)[i] = ((const float4*)Wa)[i];
    __syncthreads();

    int tx = tid & 15, ty = tid >> 4;
    int c0 = tx * 4, n0 = ty * 2;
    float at[2][4] = {{0.f}}, as_[2][4] = {{0.f}};

    // pass 1: at += meanT . Wa
    #pragma unroll 8
    for (int k = 0; k < 64; k++) {
        float2 a2 = *(const float2*)&sA[k*LDN + n0];
        float4 w4 = *(const float4*)&sW[k*64 + c0];
        float av[2] = {a2.x, a2.y};
        float wv[4] = {w4.x, w4.y, w4.z, w4.w};
        #pragma unroll
        for (int i2 = 0; i2 < 2; i2++)
            #pragma unroll
            for (int j = 0; j < 4; j++) at[i2][j] += av[i2] * wv[j];
    }
    __syncthreads();
    for (int i = tid; i < 1024; i += 256) ((float4*)sW)[i] = ((const float4*)Wr)[i];
    __syncthreads();

    // pass 2: at += hT . Wr
    #pragma unroll 8
    for (int k = 0; k < 64; k++) {
        float2 b2 = *(const float2*)&sB[k*LDN + n0];
        float4 w4 = *(const float4*)&sW[k*64 + c0];
        float bv[2] = {b2.x, b2.y};
        float wv[4] = {w4.x, w4.y, w4.z, w4.w};
        #pragma unroll
        for (int i2 = 0; i2 < 2; i2++)
            #pragma unroll
            for (int j = 0; j < 4; j++) at[i2][j] += bv[i2] * wv[j];
    }
    __syncthreads();
    for (int i = tid; i < 1024; i += 256) ((float4*)sW)[i] = ((const float4*)Wl)[i];
    __syncthreads();

    // pass 3: as = hT . Wl
    #pragma unroll 8
    for (int k = 0; k < 64; k++) {
        float2 b2 = *(const float2*)&sB[k*LDN + n0];
        float4 w4 = *(const float4*)&sW[k*64 + c0];
        float bv[2] = {b2.x, b2.y};
        float wv[4] = {w4.x, w4.y, w4.z, w4.w};
        #pragma unroll
        for (int i2 = 0; i2 < 2; i2++)
            #pragma unroll
            for (int j = 0; j < 4; j++) as_[i2][j] += bv[i2] * wv[j];
    }
    __syncthreads();

    // stage outputs into tile smem (rows 32 x 65)
    float* sO1 = sA;
    float* sO2 = sB;
    #pragma unroll
    for (int i2 = 0; i2 < 2; i2++)
        #pragma unroll
        for (int j = 0; j < 4; j++) {
            sO1[(n0+i2)*65 + c0 + j] = at[i2][j] + ba[c0 + j];
            sO2[(n0+i2)*65 + c0 + j] = as_[i2][j] + bl[c0 + j];
        }
    __syncthreads();

    // l2norm(sO1) + sO2 -> g_hpre ; per-warp BN partials -> sRed, tree -> g_part
    int warp = tid >> 5, lane = tid & 31;
    float cs0 = 0.f, css0 = 0.f, cs1 = 0.f, css1 = 0.f;
    for (int r = warp; r < 32; r += 8) {
        int node = node0 + r;
        float t0 = sO1[r*65 + lane], t1 = sO1[r*65 + lane + 32];
        float sq = t0*t0 + t1*t1;
        #pragma unroll
        for (int off = 16; off; off >>= 1) sq += __shfl_xor_sync(0xffffffffu, sq, off);
        float inv = 1.f / (sqrtf(sq) + 1e-12f);
        float hp0 = t0 * inv + sO2[r*65 + lane];
        float hp1 = t1 * inv + sO2[r*65 + lane + 32];
        if (node < NN) {
            g_hpre[(size_t)node*64 + lane]      = hp0;
            g_hpre[(size_t)node*64 + lane + 32] = hp1;
            cs0 += hp0; css0 += hp0*hp0;
            cs1 += hp1; css1 += hp1*hp1;
        }
    }
    sRed[warp*128 + lane]       = cs0;
    sRed[warp*128 + lane + 32]  = cs1;
    sRed[warp*128 + 64 + lane]      = css0;
    sRed[warp*128 + 64 + lane + 32] = css1;
    __syncthreads();
    if (tid < 128) {
        float s = 0.f;
        #pragma unroll
        for (int w = 0; w < 8; w++) s += sRed[w*128 + tid];
        g_part[(size_t)blockIdx.x * 128 + tid] = s;
    }
}

// ---------------- BN finalize: reduce g_part -> g_bn ----------------
__global__ void __launch_bounds__(1024) k_bnfin(
    const float* __restrict__ gamma, const float* __restrict__ beta)
{
    __shared__ float sAcc[1024];
    int tid = threadIdx.x;
    int c = tid & 127, grp = tid >> 7;   // 8 groups
    float s = 0.f;
    for (int b = grp; b < GEMM_BLOCKS; b += 8) s += g_part[(size_t)b * 128 + c];
    sAcc[grp * 128 + c] = s;
    __syncthreads();
    if (tid < 128) {
        float t = 0.f;
        #pragma unroll
        for (int g = 0; g < 8; g++) t += sAcc[g*128 + tid];
        sAcc[tid] = t;
    }
    __syncthreads();
    if (tid < 64) {
        float mu  = sAcc[tid] / (float)NN;
        float var = sAcc[64 + tid] / (float)NN - mu * mu;
        float rs  = 1.f / sqrtf(var + 1e-5f);
        float sc  = rs * gamma[tid];
        g_bn[tid] = sc;
        g_bn[64 + tid] = beta[tid] - mu * sc;
    }
}

// 16-slot butterfly multi-reduce: lane ends with full sum for code CODE(lane)
#define XSTEP(OFF, HALF) { \
    bool hi_ = (lane & OFF) != 0; \
    _Pragma("unroll") \
    for (int i_ = 0; i_ < HALF; i_++) { \
        float send_ = hi_ ? p[i_] : p[i_ + HALF]; \
        float recv_ = __shfl_xor_sync(0xffffffffu, send_, OFF); \
        p[i_] = (hi_ ? p[i_ + HALF] : p[i_]) + recv_; \
    } }
#define REDUCE16() XSTEP(1,8) XSTEP(2,4) XSTEP(4,2) XSTEP(8,1) \
    p[0] += __shfl_xor_sync(0xffffffffu, p[0], 16);

// ---------------- fused: BN apply + relu + xlocal + residual-VQ (+gnn head) --------
__global__ void __launch_bounds__(256) k_nodeB(
    const float* __restrict__ cbl, int layer,
    const float* __restrict__ Wg, const float* __restrict__ bg,
    float* __restrict__ out)
{
    __shared__ float sCb[48 * 65];
    __shared__ float sWg[16 * 65];
    __shared__ float sBn[128];
    __shared__ float sLoss[8];
    int tid = threadIdx.x, warp = tid >> 5, lane = tid & 31;
    if (tid < 128) sBn[tid] = g_bn[tid];
    for (int rid = warp; rid < 48; rid += 8) {
        float v0 = cbl[rid*64 + lane], v1 = cbl[rid*64 + lane + 32];
        float sq = v0*v0 + v1*v1;
        #pragma unroll
        for (int off = 16; off; off >>= 1) sq += __shfl_xor_sync(0xffffffffu, sq, off);
        float inv = 1.f / (sqrtf(sq) + 1e-12f);
        sCb[rid*65 + lane]      = v0 * inv;
        sCb[rid*65 + lane + 32] = v1 * inv;
    }
    for (int i = tid; i < 16*65; i += 256) sWg[i] = 0.f;
    __syncthreads();
    if (layer == 2) {
        for (int i = tid; i < 9*64; i += 256) {
            int j = i / 64, c = i - j*64;
            sWg[j*65 + c] = Wg[c*9 + j];   // transpose [64,9] -> [9,64]
        }
    }
    __syncthreads();

    int mycode = ((lane&1)<<3) | ((lane&2)<<1) | ((lane&4)>>1) | ((lane&8)>>3);
    float lossAcc = 0.f;
    int stride = gridDim.x * 8;
    for (int n = blockIdx.x * 8 + warp; n < NN; n += stride) {
        size_t base = (size_t)n * 64;
        float hp0 = g_hpre[base + lane], hp1 = g_hpre[base + lane + 32];
        float h0 = fmaxf(0.f, fmaf(hp0, sBn[lane],      sBn[64 + lane]));
        float h1 = fmaxf(0.f, fmaf(hp1, sBn[lane + 32], sBn[96 + lane]));
        float xl0 = g_xlocal[base + lane] + h0;
        float xl1 = g_xlocal[base + lane + 32] + h1;
        g_xlocal[base + lane] = xl0;
        g_xlocal[base + lane + 32] = xl1;
        g_h[base + lane] = h0;
        g_h[base + lane + 32] = h1;
        float r0 = h0, r1 = h1;
        #pragma unroll
        for (int r = 0; r < 3; r++) {
            float p[16];
            #pragma unroll
            for (int j = 0; j < 16; j++) {
                const float* cb = &sCb[(r*16 + j) * 65];
                p[j] = r0 * cb[lane] + r1 * cb[lane + 32];
            }
            REDUCE16();
            float bs = p[0]; int best = mycode;
            #pragma unroll
            for (int off = 16; off; off >>= 1) {
                float os = __shfl_xor_sync(0xffffffffu, bs, off);
                int   oc = __shfl_xor_sync(0xffffffffu, best, off);
                if (os > bs || (os == bs && oc < best)) { bs = os; best = oc; }
            }
            const float* cq = &sCb[(r*16 + best) * 65];
            float q0 = cq[lane], q1 = cq[lane + 32];
            float d0 = q0 - r0, d1 = q1 - r1;
            lossAcc += d0*d0 + d1*d1;
            r0 -= q0; r1 -= q1;
            if (lane == 0) out[IDS_OFF + (size_t)n*9 + layer*3 + r] = (float)best;
        }
        if (layer == 2) {
            float p[16];
            #pragma unroll
            for (int j = 0; j < 16; j++) {
                const float* wrow = &sWg[j * 65];
                p[j] = xl0 * wrow[lane] + xl1 * wrow[lane + 32];
            }
            REDUCE16();
            if (lane < 16 && mycode < 9)
                out[GNN_OFF + (size_t)n*9 + mycode] = p[0] + bg[mycode];
        }
    }
    #pragma unroll
    for (int off = 16; off; off >>= 1) lossAcc += __shfl_xor_sync(0xffffffffu, lossAcc, off);
    if (lane == 0) sLoss[warp] = lossAcc;
    __syncthreads();
    if (tid == 0) {
        float s = 0.f;
        #pragma unroll
        for (int w = 0; w < 8; w++) s += sLoss[w];
        g_cpart[layer * NODEB_BLOCKS + blockIdx.x] = s;
    }
}

// ---------------- pred head: xlocal @ Wp + bp (tiled GEMM) + commit write ----------
#define LDT 72
__global__ void __launch_bounds__(256) k_pred(
    const float* __restrict__ Wp, const float* __restrict__ bp,
    float* __restrict__ out)
{
    __shared__ float sW[4096];
    __shared__ float sX[64 * LDT];
    int tid = threadIdx.x;
    int node0 = blockIdx.x * 64;
    for (int i = tid; i < 1024; i += 256) ((float4*)sW)[i] = ((const float4*)Wp)[i];
    for (int i = tid; i < 1024; i += 256) {
        int n = i >> 4, kc = i & 15;
        int node = node0 + n;
        float4 v = make_float4(0.f, 0.f, 0.f, 0.f);
        if (node < NN) v = *(const float4*)(g_xlocal + (size_t)node*64 + kc*4);
        int kb = kc * 4;
        sX[(kb+0)*LDT+n] = v.x; sX[(kb+1)*LDT+n] = v.y;
        sX[(kb+2)*LDT+n] = v.z; sX[(kb+3)*LDT+n] = v.w;
    }
    __syncthreads();
    int tx = tid & 15, ty = tid >> 4, c0 = tx*4, n0 = ty*4;
    float acc[4][4] = {{0.f}};
    #pragma unroll 8
    for (int k = 0; k < 64; k++) {
        float4 a4 = *(const float4*)&sX[k*LDT + n0];
        float4 w4 = *(const float4*)&sW[k*64 + c0];
        float av[4] = {a4.x, a4.y, a4.z, a4.w};
        float wv[4] = {w4.x, w4.y, w4.z, w4.w};
        #pragma unroll
        for (int i2 = 0; i2 < 4; i2++)
            #pragma unroll
            for (int j = 0; j < 4; j++) acc[i2][j] += av[i2] * wv[j];
    }
    float4 bb = *(const float4*)(bp + c0);
    float bv[4] = {bb.x, bb.y, bb.z, bb.w};
    #pragma unroll
    for (int i2 = 0; i2 < 4; i2++) {
        int node = node0 + n0 + i2;
        if (node < NN) {
            float4 o = make_float4(acc[i2][0]+bv[0], acc[i2][1]+bv[1],
                                   acc[i2][2]+bv[2], acc[i2][3]+bv[3]);
            *(float4*)(out + (size_t)node*64 + c0) = o;
        }
    }
    if (blockIdx.x == 0) {
        int lane = tid & 31;
        if (tid < 32) {
            float s = 0.f;
            for (int i = lane; i < 3 * NODEB_BLOCKS; i += 32) s += g_cpart[i];
            #pragma unroll
            for (int off = 16; off; off >>= 1) s += __shfl_xor_sync(0xffffffffu, s, off);
            if (lane == 0) out[COMMIT_OFF] = s * (0.25f / (float)(NN * 64));
        }
    }
}

// ---------------- launch ----------------
extern "C" void kernel_launch(void* const* d_in, const int* in_sizes, int n_in,
                              void* d_out, int out_size) {
    const float* x       = (const float*)d_in[0];
    const void*  eiv     = d_in[1];
    const float* Wa      = (const float*)d_in[2];
    const float* ba      = (const float*)d_in[3];
    const float* Wr      = (const float*)d_in[4];
    const float* Wl      = (const float*)d_in[5];
    const float* bl      = (const float*)d_in[6];
    const float* gamma   = (const float*)d_in[7];
    const float* beta    = (const float*)d_in[8];
    const float* cbs     = (const float*)d_in[9];
    const float* Wp      = (const float*)d_in[10];
    const float* bp      = (const float*)d_in[11];
    const float* Wg      = (const float*)d_in[12];
    const float* bg      = (const float*)d_in[13];
    float* out = (float*)d_out;

    k_zero_init<<<(NN*64 + 255)/256, 256>>>();
    k_detect<<<1, 32>>>((const int*)eiv);
    k_prep<<<(NE + 255)/256, 256>>>(eiv);
    k_scan<<<1, 1024>>>();
    k_fill<<<(NE + 255)/256, 256>>>();

    for (int i = 0; i < 3; i++) {
        k_gather<<<(NN*32 + 255)/256, 256>>>(x, i);
        k_gemmA<<<GEMM_BLOCKS, 256>>>(x, i,
            Wa + i*4096, Wr + i*4096, Wl + i*4096, ba + i*64, bl + i*64);
        k_bnfin<<<1, 1024>>>(gamma + i*64, beta + i*64);
        k_nodeB<<<NODEB_BLOCKS, 256>>>(cbs + i*3*16*64, i, Wg, bg, out);
    }
    k_pred<<<(NN + 63)/64, 256>>>(Wp, bp, out);
}

// round 8
// speedup vs baseline: 1.2705x; 1.2705x over previous
#include <cuda_runtime.h>

#define NN 100000
#define NE 1000000

#define GEMM_BLOCKS ((NN + 31) / 32)      // 3125
#define NODEB_BLOCKS 1480
#define SCAN_BLOCKS ((NN + 1023) / 1024)  // 98

#define COMMIT_OFF (NN*64)
#define IDS_OFF (COMMIT_OFF+1)
#define GNN_OFF (IDS_OFF + NN*9)

// ---------------- scratch (__device__ globals; no allocation allowed) ----------------
__device__ __align__(16) float g_summed[NN*64];
__device__ __align__(16) float g_h[NN*64];
__device__ __align__(16) float g_hpre[NN*64];
__device__ __align__(16) float g_xlocal[NN*64];
__device__ int   g_srcI[NE];
__device__ int   g_dstI[NE];
__device__ int   g_csr[NE];
__device__ int   g_deg[NN];
__device__ int   g_fill[NN];
__device__ int   g_rowstart[NN + 1];
__device__ int   g_bsum[SCAN_BLOCKS];
__device__ int   g_boff[SCAN_BLOCKS];
__device__ float g_cinv[NN];
__device__ float g_part[GEMM_BLOCKS * 128];   // per-block BN partials
__device__ float g_cpart[3 * NODEB_BLOCKS];   // per-block commit partials
__device__ float g_bn[128];                   // [0:64) scale, [64:128) shift
__device__ int   g_is64;

// ---------------- init: zero degree counters ----------------
__global__ void k_zero_init() {
    int i = blockIdx.x * blockDim.x + threadIdx.x;
    if (i < NN) g_deg[i] = 0;
}

// detect edge_index dtype: int64 values < 2^31 have zero hi-words at odd int32 slots
__global__ void k_detect(const int* __restrict__ ei32) {
    int lane = threadIdx.x & 31;
    int orv = 0;
    for (int i = lane; i < 1024; i += 32) orv |= ei32[2*i + 1];
    #pragma unroll
    for (int off = 16; off; off >>= 1) orv |= __shfl_xor_sync(0xffffffffu, orv, off);
    if (lane == 0) g_is64 = (orv == 0) ? 1 : 0;
}

// one-time: indices -> int32 arrays + integer degree count (dtype-agnostic)
__global__ void k_prep(const void* __restrict__ eiv) {
    int e = blockIdx.x * blockDim.x + threadIdx.x;
    if (e < NE) {
        int s, d;
        if (g_is64) {
            const long long* ei = (const long long*)eiv;
            s = (int)ei[e];
            d = (int)ei[NE + e];
        } else {
            const int* ei = (const int*)eiv;
            s = ei[e];
            d = ei[NE + e];
        }
        g_srcI[e] = s;
        g_dstI[e] = d;
        atomicAdd(&g_deg[d], 1);
    }
}

// ---------------- parallel scan (3 phases) ----------------
// A: per-block Hillis-Steele scan of 1024 degrees; local exclusive -> rowstart
__global__ void __launch_bounds__(1024) k_scanA() {
    __shared__ int ss[1024];
    int t = threadIdx.x;
    int node = blockIdx.x * 1024 + t;
    int d = (node < NN) ? g_deg[node] : 0;
    ss[t] = d;
    __syncthreads();
    #pragma unroll
    for (int off = 1; off < 1024; off <<= 1) {
        int v = (t >= off) ? ss[t - off] : 0;
        __syncthreads();
        ss[t] += v;
        __syncthreads();
    }
    if (node < NN) g_rowstart[node] = ss[t] - d;   // local exclusive
    if (t == 1023) g_bsum[blockIdx.x] = ss[1023];
}

// B: single small block scans the 98 block sums (exclusive)
__global__ void __launch_bounds__(128) k_scanB() {
    __shared__ int ss[128];
    int t = threadIdx.x;
    int v = (t < SCAN_BLOCKS) ? g_bsum[t] : 0;
    ss[t] = v;
    __syncthreads();
    #pragma unroll
    for (int off = 1; off < 128; off <<= 1) {
        int u = (t >= off) ? ss[t - off] : 0;
        __syncthreads();
        ss[t] += u;
        __syncthreads();
    }
    if (t < SCAN_BLOCKS) g_boff[t] = ss[t] - v;    // exclusive
}

// C: add block offsets, compute cinv, zero fill counters
__global__ void k_scanC() {
    int i = blockIdx.x * blockDim.x + threadIdx.x;
    if (i < NN) {
        g_rowstart[i] += g_boff[i >> 10];
        int d = g_deg[i];
        g_cinv[i] = 1.f / (float)(d > 0 ? d : 1);
        g_fill[i] = 0;
    }
    if (i == 0) g_rowstart[NN] = NE;   // every edge has an in-range destination
}

// counting-sort edges into CSR by destination
__global__ void k_fill() {
    int e = blockIdx.x * blockDim.x + threadIdx.x;
    if (e < NE) {
        int d = g_dstI[e];
        int pos = g_rowstart[d] + atomicAdd(&g_fill[d], 1);
        g_csr[pos] = g_srcI[e];
    }
}

// ---------------- gather: summed[n] = sum over incoming edges of h[src] -----------
__global__ void __launch_bounds__(256) k_gather(const float* __restrict__ x, int layer) {
    const float* __restrict__ h = layer ? g_h : x;
    int gw = (blockIdx.x * blockDim.x + threadIdx.x) >> 5;
    int lane = threadIdx.x & 31;
    if (gw >= NN) return;
    int beg = g_rowstart[gw], end = g_rowstart[gw + 1];
    float a0 = 0.f, a1 = 0.f;
    for (int j = beg; j < end; j++) {
        int s = g_csr[j];
        const float* row = h + (size_t)s * 64;
        a0 += row[lane];
        a1 += row[lane + 32];
    }
    g_summed[(size_t)gw * 64 + lane]      = a0;
    g_summed[(size_t)gw * 64 + lane + 32] = a1;
}

// ---------------- fused: mean@Wa+ba + h@Wr -> l2norm -> + h@Wl+bl ; BN partials ----
// 32 nodes x 64 channels per block, 256 threads, 2x4 microtile, one weight at a time.
#define LDN 34
__global__ void __launch_bounds__(256) k_gemmA(
    const float* __restrict__ x, int layer,
    const float* __restrict__ Wa, const float* __restrict__ Wr,
    const float* __restrict__ Wl,
    const float* __restrict__ ba, const float* __restrict__ bl)
{
    const float* __restrict__ hin = layer ? g_h : x;
    __shared__ float sW[4096];        // one 64x64 weight
    __shared__ float sA[64 * LDN];    // meanT [k][n]
    __shared__ float sB[64 * LDN];    // hT    [k][n]
    __shared__ float sRed[8 * 128];   // per-warp stat partials

    int tid = threadIdx.x;
    int node0 = blockIdx.x * 32;

    for (int i = tid; i < 512; i += 256) {
        int n = i >> 4, kc = i & 15;
        int node = node0 + n;
        float4 mv = make_float4(0.f, 0.f, 0.f, 0.f), hv = mv;
        if (node < NN) {
            float ci = g_cinv[node];
            float4 s4 = *(const float4*)(g_summed + (size_t)node * 64 + kc * 4);
            mv = make_float4(s4.x * ci, s4.y * ci, s4.z * ci, s4.w * ci);
            hv = *(const float4*)(hin + (size_t)node * 64 + kc * 4);
        }
        int kb = kc * 4;
        sA[(kb+0)*LDN+n] = mv.x; sA[(kb+1)*LDN+n] = mv.y;
        sA[(kb+2)*LDN+n] = mv.z; sA[(kb+3)*LDN+n] = mv.w;
        sB[(kb+0)*LDN+n] = hv.x; sB[(kb+1)*LDN+n] = hv.y;
        sB[(kb+2)*LDN+n] = hv.z; sB[(kb+3)*LDN+n] = hv.w;
    }
    for (int i = tid; i < 1024; i += 256) ((float4*)sW)[i] = ((const float4*)Wa)[i];
    __syncthreads();

    int tx = tid & 15, ty = tid >> 4;
    int c0 = tx * 4, n0 = ty * 2;
    float at[2][4] = {{0.f}}, as_[2][4] = {{0.f}};

    #pragma unroll 8
    for (int k = 0; k < 64; k++) {
        float2 a2 = *(const float2*)&sA[k*LDN + n0];
        float4 w4 = *(const float4*)&sW[k*64 + c0];
        float av[2] = {a2.x, a2.y};
        float wv[4] = {w4.x, w4.y, w4.z, w4.w};
        #pragma unroll
        for (int i2 = 0; i2 < 2; i2++)
            #pragma unroll
            for (int j = 0; j < 4; j++) at[i2][j] += av[i2] * wv[j];
    }
    __syncthreads();
    for (int i = tid; i < 1024; i += 256) ((float4*)sW)[i] = ((const float4*)Wr)[i];
    __syncthreads();

    #pragma unroll 8
    for (int k = 0; k < 64; k++) {
        float2 b2 = *(const float2*)&sB[k*LDN + n0];
        float4 w4 = *(const float4*)&sW[k*64 + c0];
        float bv[2] = {b2.x, b2.y};
        float wv[4] = {w4.x, w4.y, w4.z, w4.w};
        #pragma unroll
        for (int i2 = 0; i2 < 2; i2++)
            #pragma unroll
            for (int j = 0; j < 4; j++) at[i2][j] += bv[i2] * wv[j];
    }
    __syncthreads();
    for (int i = tid; i < 1024; i += 256) ((float4*)sW)[i] = ((const float4*)Wl)[i];
    __syncthreads();

    #pragma unroll 8
    for (int k = 0; k < 64; k++) {
        float2 b2 = *(const float2*)&sB[k*LDN + n0];
        float4 w4 = *(const float4*)&sW[k*64 + c0];
        float bv[2] = {b2.x, b2.y};
        float wv[4] = {w4.x, w4.y, w4.z, w4.w};
        #pragma unroll
        for (int i2 = 0; i2 < 2; i2++)
            #pragma unroll
            for (int j = 0; j < 4; j++) as_[i2][j] += bv[i2] * wv[j];
    }
    __syncthreads();

    float* sO1 = sA;
    float* sO2 = sB;
    #pragma unroll
    for (int i2 = 0; i2 < 2; i2++)
        #pragma unroll
        for (int j = 0; j < 4; j++) {
            sO1[(n0+i2)*65 + c0 + j] = at[i2][j] + ba[c0 + j];
            sO2[(n0+i2)*65 + c0 + j] = as_[i2][j] + bl[c0 + j];
        }
    __syncthreads();

    int warp = tid >> 5, lane = tid & 31;
    float cs0 = 0.f, css0 = 0.f, cs1 = 0.f, css1 = 0.f;
    for (int r = warp; r < 32; r += 8) {
        int node = node0 + r;
        float t0 = sO1[r*65 + lane], t1 = sO1[r*65 + lane + 32];
        float sq = t0*t0 + t1*t1;
        #pragma unroll
        for (int off = 16; off; off >>= 1) sq += __shfl_xor_sync(0xffffffffu, sq, off);
        float inv = 1.f / (sqrtf(sq) + 1e-12f);
        float hp0 = t0 * inv + sO2[r*65 + lane];
        float hp1 = t1 * inv + sO2[r*65 + lane + 32];
        if (node < NN) {
            g_hpre[(size_t)node*64 + lane]      = hp0;
            g_hpre[(size_t)node*64 + lane + 32] = hp1;
            cs0 += hp0; css0 += hp0*hp0;
            cs1 += hp1; css1 += hp1*hp1;
        }
    }
    sRed[warp*128 + lane]       = cs0;
    sRed[warp*128 + lane + 32]  = cs1;
    sRed[warp*128 + 64 + lane]      = css0;
    sRed[warp*128 + 64 + lane + 32] = css1;
    __syncthreads();
    if (tid < 128) {
        float s = 0.f;
        #pragma unroll
        for (int w = 0; w < 8; w++) s += sRed[w*128 + tid];
        g_part[(size_t)blockIdx.x * 128 + tid] = s;
    }
}

// ---------------- BN finalize: reduce g_part -> g_bn ----------------
__global__ void __launch_bounds__(1024) k_bnfin(
    const float* __restrict__ gamma, const float* __restrict__ beta)
{
    __shared__ float sAcc[1024];
    int tid = threadIdx.x;
    int c = tid & 127, grp = tid >> 7;   // 8 groups
    float s = 0.f;
    for (int b = grp; b < GEMM_BLOCKS; b += 8) s += g_part[(size_t)b * 128 + c];
    sAcc[grp * 128 + c] = s;
    __syncthreads();
    if (tid < 128) {
        float t = 0.f;
        #pragma unroll
        for (int g = 0; g < 8; g++) t += sAcc[g*128 + tid];
        sAcc[tid] = t;
    }
    __syncthreads();
    if (tid < 64) {
        float mu  = sAcc[tid] / (float)NN;
        float var = sAcc[64 + tid] / (float)NN - mu * mu;
        float rs  = 1.f / sqrtf(var + 1e-5f);
        float sc  = rs * gamma[tid];
        g_bn[tid] = sc;
        g_bn[64 + tid] = beta[tid] - mu * sc;
    }
}

// 16-slot butterfly multi-reduce: lane ends with full sum for code CODE(lane)
#define XSTEP(OFF, HALF) { \
    bool hi_ = (lane & OFF) != 0; \
    _Pragma("unroll") \
    for (int i_ = 0; i_ < HALF; i_++) { \
        float send_ = hi_ ? p[i_] : p[i_ + HALF]; \
        float recv_ = __shfl_xor_sync(0xffffffffu, send_, OFF); \
        p[i_] = (hi_ ? p[i_ + HALF] : p[i_]) + recv_; \
    } }
#define REDUCE16() XSTEP(1,8) XSTEP(2,4) XSTEP(4,2) XSTEP(8,1) \
    p[0] += __shfl_xor_sync(0xffffffffu, p[0], 16);

// ---------------- fused: BN apply + relu + xlocal + residual-VQ (+gnn head) --------
__global__ void __launch_bounds__(256) k_nodeB(
    const float* __restrict__ cbl, int layer,
    const float* __restrict__ Wg, const float* __restrict__ bg,
    float* __restrict__ out)
{
    __shared__ float sCb[48 * 65];
    __shared__ float sWg[16 * 65];
    __shared__ float sBn[128];
    __shared__ float sLoss[8];
    int tid = threadIdx.x, warp = tid >> 5, lane = tid & 31;
    if (tid < 128) sBn[tid] = g_bn[tid];
    for (int rid = warp; rid < 48; rid += 8) {
        float v0 = cbl[rid*64 + lane], v1 = cbl[rid*64 + lane + 32];
        float sq = v0*v0 + v1*v1;
        #pragma unroll
        for (int off = 16; off; off >>= 1) sq += __shfl_xor_sync(0xffffffffu, sq, off);
        float inv = 1.f / (sqrtf(sq) + 1e-12f);
        sCb[rid*65 + lane]      = v0 * inv;
        sCb[rid*65 + lane + 32] = v1 * inv;
    }
    for (int i = tid; i < 16*65; i += 256) sWg[i] = 0.f;
    __syncthreads();
    if (layer == 2) {
        for (int i = tid; i < 9*64; i += 256) {
            int j = i / 64, c = i - j*64;
            sWg[j*65 + c] = Wg[c*9 + j];   // transpose [64,9] -> [9,64]
        }
    }
    __syncthreads();

    int mycode = ((lane&1)<<3) | ((lane&2)<<1) | ((lane&4)>>1) | ((lane&8)>>3);
    float lossAcc = 0.f;
    int stride = gridDim.x * 8;
    for (int n = blockIdx.x * 8 + warp; n < NN; n += stride) {
        size_t base = (size_t)n * 64;
        float hp0 = g_hpre[base + lane], hp1 = g_hpre[base + lane + 32];
        float h0 = fmaxf(0.f, fmaf(hp0, sBn[lane],      sBn[64 + lane]));
        float h1 = fmaxf(0.f, fmaf(hp1, sBn[lane + 32], sBn[96 + lane]));
        float xl0 = h0, xl1 = h1;
        if (layer) {
            xl0 += g_xlocal[base + lane];
            xl1 += g_xlocal[base + lane + 32];
        }
        g_xlocal[base + lane] = xl0;
        g_xlocal[base + lane + 32] = xl1;
        g_h[base + lane] = h0;
        g_h[base + lane + 32] = h1;
        float r0 = h0, r1 = h1;
        #pragma unroll
        for (int r = 0; r < 3; r++) {
            float p[16];
            #pragma unroll
            for (int j = 0; j < 16; j++) {
                const float* cb = &sCb[(r*16 + j) * 65];
                p[j] = r0 * cb[lane] + r1 * cb[lane + 32];
            }
            REDUCE16();
            float bs = p[0]; int best = mycode;
            #pragma unroll
            for (int off = 16; off; off >>= 1) {
                float os = __shfl_xor_sync(0xffffffffu, bs, off);
                int   oc = __shfl_xor_sync(0xffffffffu, best, off);
                if (os > bs || (os == bs && oc < best)) { bs = os; best = oc; }
            }
            const float* cq = &sCb[(r*16 + best) * 65];
            float q0 = cq[lane], q1 = cq[lane + 32];
            float d0 = q0 - r0, d1 = q1 - r1;
            lossAcc += d0*d0 + d1*d1;
            r0 -= q0; r1 -= q1;
            if (lane == 0) out[IDS_OFF + (size_t)n*9 + layer*3 + r] = (float)best;
        }
        if (layer == 2) {
            float p[16];
            #pragma unroll
            for (int j = 0; j < 16; j++) {
                const float* wrow = &sWg[j * 65];
                p[j] = xl0 * wrow[lane] + xl1 * wrow[lane + 32];
            }
            REDUCE16();
            if (lane < 16 && mycode < 9)
                out[GNN_OFF + (size_t)n*9 + mycode] = p[0] + bg[mycode];
        }
    }
    #pragma unroll
    for (int off = 16; off; off >>= 1) lossAcc += __shfl_xor_sync(0xffffffffu, lossAcc, off);
    if (lane == 0) sLoss[warp] = lossAcc;
    __syncthreads();
    if (tid == 0) {
        float s = 0.f;
        #pragma unroll
        for (int w = 0; w < 8; w++) s += sLoss[w];
        g_cpart[layer * NODEB_BLOCKS + blockIdx.x] = s;
    }
}

// ---------------- pred head: xlocal @ Wp + bp (tiled GEMM) + commit write ----------
#define LDT 72
__global__ void __launch_bounds__(256) k_pred(
    const float* __restrict__ Wp, const float* __restrict__ bp,
    float* __restrict__ out)
{
    __shared__ float sW[4096];
    __shared__ float sX[64 * LDT];
    int tid = threadIdx.x;
    int node0 = blockIdx.x * 64;
    for (int i = tid; i < 1024; i += 256) ((float4*)sW)[i] = ((const float4*)Wp)[i];
    for (int i = tid; i < 1024; i += 256) {
        int n = i >> 4, kc = i & 15;
        int node = node0 + n;
        float4 v = make_float4(0.f, 0.f, 0.f, 0.f);
        if (node < NN) v = *(const float4*)(g_xlocal + (size_t)node*64 + kc*4);
        int kb = kc * 4;
        sX[(kb+0)*LDT+n] = v.x; sX[(kb+1)*LDT+n] = v.y;
        sX[(kb+2)*LDT+n] = v.z; sX[(kb+3)*LDT+n] = v.w;
    }
    __syncthreads();
    int tx = tid & 15, ty = tid >> 4, c0 = tx*4, n0 = ty*4;
    float acc[4][4] = {{0.f}};
    #pragma unroll 8
    for (int k = 0; k < 64; k++) {
        float4 a4 = *(const float4*)&sX[k*LDT + n0];
        float4 w4 = *(const float4*)&sW[k*64 + c0];
        float av[4] = {a4.x, a4.y, a4.z, a4.w};
        float wv[4] = {w4.x, w4.y, w4.z, w4.w};
        #pragma unroll
        for (int i2 = 0; i2 < 4; i2++)
            #pragma unroll
            for (int j = 0; j < 4; j++) acc[i2][j] += av[i2] * wv[j];
    }
    float4 bb = *(const float4*)(bp + c0);
    float bv[4] = {bb.x, bb.y, bb.z, bb.w};
    #pragma unroll
    for (int i2 = 0; i2 < 4; i2++) {
        int node = node0 + n0 + i2;
        if (node < NN) {
            float4 o = make_float4(acc[i2][0]+bv[0], acc[i2][1]+bv[1],
                                   acc[i2][2]+bv[2], acc[i2][3]+bv[3]);
            *(float4*)(out + (size_t)node*64 + c0) = o;
        }
    }
    if (blockIdx.x == 0) {
        int lane = tid & 31;
        if (tid < 32) {
            float s = 0.f;
            for (int i = lane; i < 3 * NODEB_BLOCKS; i += 32) s += g_cpart[i];
            #pragma unroll
            for (int off = 16; off; off >>= 1) s += __shfl_xor_sync(0xffffffffu, s, off);
            if (lane == 0) out[COMMIT_OFF] = s * (0.25f / (float)(NN * 64));
        }
    }
}

// ---------------- launch ----------------
extern "C" void kernel_launch(void* const* d_in, const int* in_sizes, int n_in,
                              void* d_out, int out_size) {
    const float* x       = (const float*)d_in[0];
    const void*  eiv     = d_in[1];
    const float* Wa      = (const float*)d_in[2];
    const float* ba      = (const float*)d_in[3];
    const float* Wr      = (const float*)d_in[4];
    const float* Wl      = (const float*)d_in[5];
    const float* bl      = (const float*)d_in[6];
    const float* gamma   = (const float*)d_in[7];
    const float* beta    = (const float*)d_in[8];
    const float* cbs     = (const float*)d_in[9];
    const float* Wp      = (const float*)d_in[10];
    const float* bp      = (const float*)d_in[11];
    const float* Wg      = (const float*)d_in[12];
    const float* bg      = (const float*)d_in[13];
    float* out = (float*)d_out;

    k_zero_init<<<(NN + 255)/256, 256>>>();
    k_detect<<<1, 32>>>((const int*)eiv);
    k_prep<<<(NE + 255)/256, 256>>>(eiv);
    k_scanA<<<SCAN_BLOCKS, 1024>>>();
    k_scanB<<<1, 128>>>();
    k_scanC<<<(NN + 255)/256, 256>>>();
    k_fill<<<(NE + 255)/256, 256>>>();

    for (int i = 0; i < 3; i++) {
        k_gather<<<(NN*32 + 255)/256, 256>>>(x, i);
        k_gemmA<<<GEMM_BLOCKS, 256>>>(x, i,
            Wa + i*4096, Wr + i*4096, Wl + i*4096, ba + i*64, bl + i*64);
        k_bnfin<<<1, 1024>>>(gamma + i*64, beta + i*64);
        k_nodeB<<<NODEB_BLOCKS, 256>>>(cbs + i*3*16*64, i, Wg, bg, out);
    }
    k_pred<<<(NN + 63)/64, 256>>>(Wp, bp, out);
}

// round 10
// speedup vs baseline: 1.4043x; 1.1054x over previous
#include <cuda_runtime.h>

#define NN 100000
#define NE 1000000

#define GB ((NN + 63) / 64)               // 1563 gemm blocks
#define NODEB_BLOCKS 1480
#define SCANB ((NN + 1023) / 1024)        // 98

#define COMMIT_OFF (NN*64)
#define IDS_OFF (COMMIT_OFF+1)
#define GNN_OFF (IDS_OFF + NN*9)

// ---------------- scratch (__device__ globals; no allocation allowed) ----------------
__device__ __align__(16) float g_h[NN*64];
__device__ __align__(16) float g_hpre[NN*64];
__device__ __align__(16) float g_xlocal[NN*64];
__device__ int   g_csr[NE];
__device__ int   g_deg[NN];
__device__ int   g_fill[NN];
__device__ int   g_rowstart[NN + 1];
__device__ int   g_bsum[SCANB];
__device__ float g_cinv[NN];
__device__ float g_part[GB * 128];            // per-block BN partials
__device__ float g_cpart[3 * NODEB_BLOCKS];   // per-block commit partials
__device__ float g_bn[128];                   // [0:64) scale, [64:128) shift
__device__ int   g_is64;

// ---------------- init: zero degree counters + dtype detect ----------------
__global__ void k_init(const int* __restrict__ ei32) {
    int i = blockIdx.x * blockDim.x + threadIdx.x;
    if (i < NN) g_deg[i] = 0;
    if (blockIdx.x == 0 && threadIdx.x < 32) {
        int lane = threadIdx.x;
        int orv = 0;
        for (int j = lane; j < 1024; j += 32) orv |= ei32[2*j + 1];
        #pragma unroll
        for (int off = 16; off; off >>= 1) orv |= __shfl_xor_sync(0xffffffffu, orv, off);
        if (lane == 0) g_is64 = (orv == 0) ? 1 : 0;
    }
}

// degree count straight from the input edge list
__global__ void k_prep(const void* __restrict__ eiv) {
    int e = blockIdx.x * blockDim.x + threadIdx.x;
    if (e < NE) {
        int d = g_is64 ? (int)((const long long*)eiv)[NE + e]
                       : ((const int*)eiv)[NE + e];
        atomicAdd(&g_deg[d], 1);
    }
}

// per-block Hillis-Steele scan of 1024 degrees; local exclusive -> rowstart
__global__ void __launch_bounds__(1024) k_scanA() {
    __shared__ int ss[1024];
    int t = threadIdx.x;
    int node = blockIdx.x * 1024 + t;
    int d = (node < NN) ? g_deg[node] : 0;
    ss[t] = d;
    __syncthreads();
    #pragma unroll
    for (int off = 1; off < 1024; off <<= 1) {
        int v = (t >= off) ? ss[t - off] : 0;
        __syncthreads();
        ss[t] += v;
        __syncthreads();
    }
    if (node < NN) g_rowstart[node] = ss[t] - d;   // local exclusive
    if (t == 1023) g_bsum[blockIdx.x] = ss[1023];
}

// fused: scan the 98 block sums (redundantly per block) + finalize rowstart/cinv/fill
__global__ void k_scanBC() {
    __shared__ int sb[128];
    int t = threadIdx.x;
    if (t < 128) sb[t] = (t < SCANB) ? g_bsum[t] : 0;
    __syncthreads();
    #pragma unroll
    for (int off = 1; off < 128; off <<= 1) {
        int v = 0;
        if (t < 128 && t >= off) v = sb[t - off];
        __syncthreads();
        if (t < 128) sb[t] += v;                   // inclusive
        __syncthreads();
    }
    int i = blockIdx.x * blockDim.x + t;
    if (i < NN) {
        int blk = i >> 10;
        g_rowstart[i] += blk ? sb[blk - 1] : 0;
        int d = g_deg[i];
        g_cinv[i] = 1.f / (float)(d > 0 ? d : 1);
        g_fill[i] = 0;
    }
    if (i == 0) g_rowstart[NN] = NE;
}

// counting-sort edges into CSR by destination (reads input edge list directly)
__global__ void k_fill(const void* __restrict__ eiv) {
    int e = blockIdx.x * blockDim.x + threadIdx.x;
    if (e < NE) {
        int s, d;
        if (g_is64) {
            s = (int)((const long long*)eiv)[e];
            d = (int)((const long long*)eiv)[NE + e];
        } else {
            s = ((const int*)eiv)[e];
            d = ((const int*)eiv)[NE + e];
        }
        int pos = g_rowstart[d] + atomicAdd(&g_fill[d], 1);
        g_csr[pos] = s;
    }
}

// ---------------- fused layer kernel part 1 ----------------
// phase0: gather mean rows into transposed smem tile
// pass1: at = ba + meanT@Wa ; restage hT ; pass2: at += hT@Wr ; pass3: as = bl + hT@Wl
// epilogue: hpre = l2n(at) + as ; per-block BN partials
// NOTE: sT has odd-ish stride 65 -> tile reads in the k-loop MUST be scalar LDS
// (float4 would be misaligned for odd k); weight reads on sW (stride 64) are LDS.128.
__global__ void __launch_bounds__(256) k_gemmA(
    const float* __restrict__ x, int layer,
    const float* __restrict__ Wa, const float* __restrict__ Wr,
    const float* __restrict__ Wl,
    const float* __restrict__ ba, const float* __restrict__ bl)
{
    const float* __restrict__ hin = layer ? g_h : x;
    __shared__ float sT[64 * 65];     // input tile transposed [k][n] / output stage 1
    __shared__ float sW[4096];        // weight [k][c] / output stage 2
    __shared__ float sRed[8 * 128];   // per-warp stat partials

    int tid = threadIdx.x, warp = tid >> 5, lane = tid & 31;
    int node0 = blockIdx.x * 64;

    // phase0: gather (mean of neighbor h rows) -> sT transposed
    for (int r = warp * 8; r < warp * 8 + 8; r++) {
        int node = node0 + r;
        float a0 = 0.f, a1 = 0.f;
        if (node < NN) {
            int beg = g_rowstart[node], end = g_rowstart[node + 1];
            for (int j = beg; j < end; j++) {
                int s = g_csr[j];
                const float* row = hin + (size_t)s * 64;
                a0 += row[lane];
                a1 += row[lane + 32];
            }
            float ci = g_cinv[node];
            a0 *= ci; a1 *= ci;
        }
        sT[lane * 65 + r]        = a0;
        sT[(lane + 32) * 65 + r] = a1;
    }
    for (int i = tid; i < 1024; i += 256) ((float4*)sW)[i] = ((const float4*)Wa)[i];
    __syncthreads();

    int tx = tid & 15, ty = tid >> 4;
    int c0 = tx * 4, n0 = ty * 4;
    float at[4][4], as_[4][4];
    {
        float4 bb = *(const float4*)(ba + c0);
        #pragma unroll
        for (int i2 = 0; i2 < 4; i2++) {
            at[i2][0] = bb.x; at[i2][1] = bb.y; at[i2][2] = bb.z; at[i2][3] = bb.w;
        }
    }

    // pass1: at += meanT @ Wa
    #pragma unroll 8
    for (int k = 0; k < 64; k++) {
        const float* tr = &sT[k*65 + n0];
        float av[4] = {tr[0], tr[1], tr[2], tr[3]};
        float4 w4 = *(const float4*)&sW[k*64 + c0];
        float wv[4] = {w4.x, w4.y, w4.z, w4.w};
        #pragma unroll
        for (int i2 = 0; i2 < 4; i2++)
            #pragma unroll
            for (int j = 0; j < 4; j++) at[i2][j] += av[i2] * wv[j];
    }
    __syncthreads();

    // restage: sT <- own h rows (transposed), sW <- Wr
    for (int i = tid; i < 1024; i += 256) {
        int n = i >> 4, kc = i & 15;
        int node = node0 + n;
        float4 hv = make_float4(0.f, 0.f, 0.f, 0.f);
        if (node < NN) hv = *(const float4*)(hin + (size_t)node * 64 + kc * 4);
        int kb = kc * 4;
        sT[(kb+0)*65+n] = hv.x; sT[(kb+1)*65+n] = hv.y;
        sT[(kb+2)*65+n] = hv.z; sT[(kb+3)*65+n] = hv.w;
    }
    __syncthreads();
    for (int i = tid; i < 1024; i += 256) ((float4*)sW)[i] = ((const float4*)Wr)[i];
    __syncthreads();

    // pass2: at += hT @ Wr
    #pragma unroll 8
    for (int k = 0; k < 64; k++) {
        const float* tr = &sT[k*65 + n0];
        float av[4] = {tr[0], tr[1], tr[2], tr[3]};
        float4 w4 = *(const float4*)&sW[k*64 + c0];
        float wv[4] = {w4.x, w4.y, w4.z, w4.w};
        #pragma unroll
        for (int i2 = 0; i2 < 4; i2++)
            #pragma unroll
            for (int j = 0; j < 4; j++) at[i2][j] += av[i2] * wv[j];
    }
    __syncthreads();
    for (int i = tid; i < 1024; i += 256) ((float4*)sW)[i] = ((const float4*)Wl)[i];
    __syncthreads();

    // pass3: as = bl + hT @ Wl
    {
        float4 bb = *(const float4*)(bl + c0);
        #pragma unroll
        for (int i2 = 0; i2 < 4; i2++) {
            as_[i2][0] = bb.x; as_[i2][1] = bb.y; as_[i2][2] = bb.z; as_[i2][3] = bb.w;
        }
    }
    #pragma unroll 8
    for (int k = 0; k < 64; k++) {
        const float* tr = &sT[k*65 + n0];
        float av[4] = {tr[0], tr[1], tr[2], tr[3]};
        float4 w4 = *(const float4*)&sW[k*64 + c0];
        float wv[4] = {w4.x, w4.y, w4.z, w4.w};
        #pragma unroll
        for (int i2 = 0; i2 < 4; i2++)
            #pragma unroll
            for (int j = 0; j < 4; j++) as_[i2][j] += av[i2] * wv[j];
    }
    __syncthreads();

    // stage outputs: sT <- at (padded 65), sW <- as (64-wide rows; row reads conflict-free)
    #pragma unroll
    for (int i2 = 0; i2 < 4; i2++)
        #pragma unroll
        for (int j = 0; j < 4; j++) {
            sT[(n0+i2)*65 + c0 + j] = at[i2][j];
            sW[(n0+i2)*64 + c0 + j] = as_[i2][j];
        }
    __syncthreads();

    // epilogue: l2norm + skip-add -> g_hpre ; BN partials
    float cs0 = 0.f, css0 = 0.f, cs1 = 0.f, css1 = 0.f;
    for (int r = warp; r < 64; r += 8) {
        int node = node0 + r;
        float t0 = sT[r*65 + lane], t1 = sT[r*65 + lane + 32];
        float sq = t0*t0 + t1*t1;
        #pragma unroll
        for (int off = 16; off; off >>= 1) sq += __shfl_xor_sync(0xffffffffu, sq, off);
        float inv = 1.f / (sqrtf(sq) + 1e-12f);
        float hp0 = t0 * inv + sW[r*64 + lane];
        float hp1 = t1 * inv + sW[r*64 + lane + 32];
        if (node < NN) {
            g_hpre[(size_t)node*64 + lane]      = hp0;
            g_hpre[(size_t)node*64 + lane + 32] = hp1;
            cs0 += hp0; css0 += hp0*hp0;
            cs1 += hp1; css1 += hp1*hp1;
        }
    }
    sRed[warp*128 + lane]           = cs0;
    sRed[warp*128 + lane + 32]      = cs1;
    sRed[warp*128 + 64 + lane]      = css0;
    sRed[warp*128 + 64 + lane + 32] = css1;
    __syncthreads();
    if (tid < 128) {
        float s = 0.f;
        #pragma unroll
        for (int w = 0; w < 8; w++) s += sRed[w*128 + tid];
        g_part[(size_t)blockIdx.x * 128 + tid] = s;
    }
}

// ---------------- BN finalize: reduce g_part -> g_bn ----------------
__global__ void __launch_bounds__(1024) k_bnfin(
    const float* __restrict__ gamma, const float* __restrict__ beta)
{
    __shared__ float sAcc[1024];
    int tid = threadIdx.x;
    int c = tid & 127, grp = tid >> 7;   // 8 groups
    float s = 0.f;
    for (int b = grp; b < GB; b += 8) s += g_part[(size_t)b * 128 + c];
    sAcc[grp * 128 + c] = s;
    __syncthreads();
    if (tid < 128) {
        float t = 0.f;
        #pragma unroll
        for (int g = 0; g < 8; g++) t += sAcc[g*128 + tid];
        sAcc[tid] = t;
    }
    __syncthreads();
    if (tid < 64) {
        float mu  = sAcc[tid] / (float)NN;
        float var = sAcc[64 + tid] / (float)NN - mu * mu;
        float rs  = 1.f / sqrtf(var + 1e-5f);
        float sc  = rs * gamma[tid];
        g_bn[tid] = sc;
        g_bn[64 + tid] = beta[tid] - mu * sc;
    }
}

// 16-slot butterfly multi-reduce: lane ends with full sum for code CODE(lane)
#define XSTEP(OFF, HALF) { \
    bool hi_ = (lane & OFF) != 0; \
    _Pragma("unroll") \
    for (int i_ = 0; i_ < HALF; i_++) { \
        float send_ = hi_ ? p[i_] : p[i_ + HALF]; \
        float recv_ = __shfl_xor_sync(0xffffffffu, send_, OFF); \
        p[i_] = (hi_ ? p[i_ + HALF] : p[i_]) + recv_; \
    } }
#define REDUCE16() XSTEP(1,8) XSTEP(2,4) XSTEP(4,2) XSTEP(8,1) \
    p[0] += __shfl_xor_sync(0xffffffffu, p[0], 16);

// ---------------- fused: BN apply + relu + xlocal + residual-VQ (+gnn head) --------
__global__ void __launch_bounds__(256) k_nodeB(
    const float* __restrict__ cbl, int layer,
    const float* __restrict__ Wg, const float* __restrict__ bg,
    float* __restrict__ out)
{
    __shared__ float sCb[48 * 65];
    __shared__ float sWg[16 * 65];
    __shared__ float sBn[128];
    __shared__ float sLoss[8];
    int tid = threadIdx.x, warp = tid >> 5, lane = tid & 31;
    if (tid < 128) sBn[tid] = g_bn[tid];
    for (int rid = warp; rid < 48; rid += 8) {
        float v0 = cbl[rid*64 + lane], v1 = cbl[rid*64 + lane + 32];
        float sq = v0*v0 + v1*v1;
        #pragma unroll
        for (int off = 16; off; off >>= 1) sq += __shfl_xor_sync(0xffffffffu, sq, off);
        float inv = 1.f / (sqrtf(sq) + 1e-12f);
        sCb[rid*65 + lane]      = v0 * inv;
        sCb[rid*65 + lane + 32] = v1 * inv;
    }
    for (int i = tid; i < 16*65; i += 256) sWg[i] = 0.f;
    __syncthreads();
    if (layer == 2) {
        for (int i = tid; i < 9*64; i += 256) {
            int j = i / 64, c = i - j*64;
            sWg[j*65 + c] = Wg[c*9 + j];   // transpose [64,9] -> [9,64]
        }
    }
    __syncthreads();

    int mycode = ((lane&1)<<3) | ((lane&2)<<1) | ((lane&4)>>1) | ((lane&8)>>3);
    float lossAcc = 0.f;
    int stride = gridDim.x * 8;
    for (int n = blockIdx.x * 8 + warp; n < NN; n += stride) {
        size_t base = (size_t)n * 64;
        float hp0 = g_hpre[base + lane], hp1 = g_hpre[base + lane + 32];
        float h0 = fmaxf(0.f, fmaf(hp0, sBn[lane],      sBn[64 + lane]));
        float h1 = fmaxf(0.f, fmaf(hp1, sBn[lane + 32], sBn[96 + lane]));
        float xl0 = h0, xl1 = h1;
        if (layer) {
            xl0 += g_xlocal[base + lane];
            xl1 += g_xlocal[base + lane + 32];
        }
        g_xlocal[base + lane] = xl0;
        g_xlocal[base + lane + 32] = xl1;
        g_h[base + lane] = h0;
        g_h[base + lane + 32] = h1;
        float r0 = h0, r1 = h1;
        #pragma unroll
        for (int r = 0; r < 3; r++) {
            float p[16];
            #pragma unroll
            for (int j = 0; j < 16; j++) {
                const float* cb = &sCb[(r*16 + j) * 65];
                p[j] = r0 * cb[lane] + r1 * cb[lane + 32];
            }
            REDUCE16();
            // lanes l and l^16 hold identical (p[0], mycode): 4-step argmax
            float bs = p[0]; int best = mycode;
            #pragma unroll
            for (int off = 8; off; off >>= 1) {
                float os = __shfl_xor_sync(0xffffffffu, bs, off);
                int   oc = __shfl_xor_sync(0xffffffffu, best, off);
                if (os > bs || (os == bs && oc < best)) { bs = os; best = oc; }
            }
            const float* cq = &sCb[(r*16 + best) * 65];
            float q0 = cq[lane], q1 = cq[lane + 32];
            float d0 = q0 - r0, d1 = q1 - r1;
            lossAcc += d0*d0 + d1*d1;
            r0 -= q0; r1 -= q1;
            if (lane == 0) out[IDS_OFF + (size_t)n*9 + layer*3 + r] = (float)best;
        }
        if (layer == 2) {
            float p[16];
            #pragma unroll
            for (int j = 0; j < 16; j++) {
                const float* wrow = &sWg[j * 65];
                p[j] = xl0 * wrow[lane] + xl1 * wrow[lane + 32];
            }
            REDUCE16();
            if (lane < 16 && mycode < 9)
                out[GNN_OFF + (size_t)n*9 + mycode] = p[0] + bg[mycode];
        }
    }
    #pragma unroll
    for (int off = 16; off; off >>= 1) lossAcc += __shfl_xor_sync(0xffffffffu, lossAcc, off);
    if (lane == 0) sLoss[warp] = lossAcc;
    __syncthreads();
    if (tid == 0) {
        float s = 0.f;
        #pragma unroll
        for (int w = 0; w < 8; w++) s += sLoss[w];
        g_cpart[layer * NODEB_BLOCKS + blockIdx.x] = s;
    }
}

// ---------------- pred head: xlocal @ Wp + bp (tiled GEMM) + commit write ----------
#define LDT 72
__global__ void __launch_bounds__(256) k_pred(
    const float* __restrict__ Wp, const float* __restrict__ bp,
    float* __restrict__ out)
{
    __shared__ float sW[4096];
    __shared__ float sX[64 * LDT];
    int tid = threadIdx.x;
    int node0 = blockIdx.x * 64;
    for (int i = tid; i < 1024; i += 256) ((float4*)sW)[i] = ((const float4*)Wp)[i];
    for (int i = tid; i < 1024; i += 256) {
        int n = i >> 4, kc = i & 15;
        int node = node0 + n;
        float4 v = make_float4(0.f, 0.f, 0.f, 0.f);
        if (node < NN) v = *(const float4*)(g_xlocal + (size_t)node*64 + kc*4);
        int kb = kc * 4;
        sX[(kb+0)*LDT+n] = v.x; sX[(kb+1)*LDT+n] = v.y;
        sX[(kb+2)*LDT+n] = v.z; sX[(kb+3)*LDT+n] = v.w;
    }
    __syncthreads();
    int tx = tid & 15, ty = tid >> 4, c0 = tx*4, n0 = ty*4;
    float acc[4][4] = {{0.f}};
    #pragma unroll 8
    for (int k = 0; k < 64; k++) {
        float4 a4 = *(const float4*)&sX[k*LDT + n0];
        float4 w4 = *(const float4*)&sW[k*64 + c0];
        float av[4] = {a4.x, a4.y, a4.z, a4.w};
        float wv[4] = {w4.x, w4.y, w4.z, w4.w};
        #pragma unroll
        for (int i2 = 0; i2 < 4; i2++)
            #pragma unroll
            for (int j = 0; j < 4; j++) acc[i2][j] += av[i2] * wv[j];
    }
    float4 bb = *(const float4*)(bp + c0);
    float bv[4] = {bb.x, bb.y, bb.z, bb.w};
    #pragma unroll
    for (int i2 = 0; i2 < 4; i2++) {
        int node = node0 + n0 + i2;
        if (node < NN) {
            float4 o = make_float4(acc[i2][0]+bv[0], acc[i2][1]+bv[1],
                                   acc[i2][2]+bv[2], acc[i2][3]+bv[3]);
            *(float4*)(out + (size_t)node*64 + c0) = o;
        }
    }
    if (blockIdx.x == 0) {
        int lane = tid & 31;
        if (tid < 32) {
            float s = 0.f;
            for (int i = lane; i < 3 * NODEB_BLOCKS; i += 32) s += g_cpart[i];
            #pragma unroll
            for (int off = 16; off; off >>= 1) s += __shfl_xor_sync(0xffffffffu, s, off);
            if (lane == 0) out[COMMIT_OFF] = s * (0.25f / (float)(NN * 64));
        }
    }
}

// ---------------- launch ----------------
extern "C" void kernel_launch(void* const* d_in, const int* in_sizes, int n_in,
                              void* d_out, int out_size) {
    const float* x       = (const float*)d_in[0];
    const void*  eiv     = d_in[1];
    const float* Wa      = (const float*)d_in[2];
    const float* ba      = (const float*)d_in[3];
    const float* Wr      = (const float*)d_in[4];
    const float* Wl      = (const float*)d_in[5];
    const float* bl      = (const float*)d_in[6];
    const float* gamma   = (const float*)d_in[7];
    const float* beta    = (const float*)d_in[8];
    const float* cbs     = (const float*)d_in[9];
    const float* Wp      = (const float*)d_in[10];
    const float* bp      = (const float*)d_in[11];
    const float* Wg      = (const float*)d_in[12];
    const float* bg      = (const float*)d_in[13];
    float* out = (float*)d_out;

    k_init<<<(NN + 255)/256, 256>>>((const int*)eiv);
    k_prep<<<(NE + 255)/256, 256>>>(eiv);
    k_scanA<<<SCANB, 1024>>>();
    k_scanBC<<<(NN + 255)/256, 256>>>();
    k_fill<<<(NE + 255)/256, 256>>>(eiv);

    for (int i = 0; i < 3; i++) {
        k_gemmA<<<GB, 256>>>(x, i,
            Wa + i*4096, Wr + i*4096, Wl + i*4096, ba + i*64, bl + i*64);
        k_bnfin<<<1, 1024>>>(gamma + i*64, beta + i*64);
        k_nodeB<<<NODEB_BLOCKS, 256>>>(cbs + i*3*16*64, i, Wg, bg, out);
    }
    k_pred<<<(NN + 63)/64, 256>>>(Wp, bp, out);
}

// round 11
// speedup vs baseline: 1.5076x; 1.0736x over previous
#include <cuda_runtime.h>

#define NN 100000
#define NE 1000000

#define GB ((NN + 63) / 64)               // 1563 gemm blocks
#define NODEB_BLOCKS 1480
#define SCANB ((NN + 1023) / 1024)        // 98

#define COMMIT_OFF (NN*64)
#define IDS_OFF (COMMIT_OFF+1)
#define GNN_OFF (IDS_OFF + NN*9)

// ---------------- packed f32x2 helpers ----------------
__device__ __forceinline__ unsigned long long pk2(float lo, float hi) {
    unsigned long long r;
    asm("mov.b64 %0, {%1,%2};" : "=l"(r) : "f"(lo), "f"(hi));
    return r;
}
__device__ __forceinline__ float2 upk2(unsigned long long v) {
    float2 f;
    asm("mov.b64 {%0,%1}, %2;" : "=f"(f.x), "=f"(f.y) : "l"(v));
    return f;
}
__device__ __forceinline__ void fma2(unsigned long long& d,
                                     unsigned long long a, unsigned long long b) {
    asm("fma.rn.f32x2 %0, %1, %2, %0;" : "+l"(d) : "l"(a), "l"(b));
}

// ---------------- scratch (__device__ globals; no allocation allowed) ----------------
__device__ __align__(16) float g_h[NN*64];
__device__ __align__(16) float g_hpre[NN*64];
__device__ __align__(16) float g_xlocal[NN*64];
__device__ int   g_csr[NE];
__device__ int   g_deg[NN];
__device__ int   g_fill[NN];
__device__ int   g_rowstart[NN + 1];
__device__ int   g_bsum[SCANB];
__device__ float g_cinv[NN];
__device__ float g_part[GB * 128];            // per-block BN partials
__device__ float g_cpart[3 * NODEB_BLOCKS];   // per-block commit partials
__device__ float g_bn[128];                   // [0:64) scale, [64:128) shift
__device__ int   g_is64;

// ---------------- init: zero degree counters + dtype detect ----------------
__global__ void k_init(const int* __restrict__ ei32) {
    int i = blockIdx.x * blockDim.x + threadIdx.x;
    if (i < NN) g_deg[i] = 0;
    if (blockIdx.x == 0 && threadIdx.x < 32) {
        int lane = threadIdx.x;
        int orv = 0;
        for (int j = lane; j < 1024; j += 32) orv |= ei32[2*j + 1];
        #pragma unroll
        for (int off = 16; off; off >>= 1) orv |= __shfl_xor_sync(0xffffffffu, orv, off);
        if (lane == 0) g_is64 = (orv == 0) ? 1 : 0;
    }
}

// degree count straight from the input edge list
__global__ void k_prep(const void* __restrict__ eiv) {
    int e = blockIdx.x * blockDim.x + threadIdx.x;
    if (e < NE) {
        int d = g_is64 ? (int)((const long long*)eiv)[NE + e]
                       : ((const int*)eiv)[NE + e];
        atomicAdd(&g_deg[d], 1);
    }
}

// per-block Hillis-Steele scan of 1024 degrees; local exclusive -> rowstart
__global__ void __launch_bounds__(1024) k_scanA() {
    __shared__ int ss[1024];
    int t = threadIdx.x;
    int node = blockIdx.x * 1024 + t;
    int d = (node < NN) ? g_deg[node] : 0;
    ss[t] = d;
    __syncthreads();
    #pragma unroll
    for (int off = 1; off < 1024; off <<= 1) {
        int v = (t >= off) ? ss[t - off] : 0;
        __syncthreads();
        ss[t] += v;
        __syncthreads();
    }
    if (node < NN) g_rowstart[node] = ss[t] - d;   // local exclusive
    if (t == 1023) g_bsum[blockIdx.x] = ss[1023];
}

// fused: scan the 98 block sums (redundantly per block) + finalize rowstart/cinv/fill
__global__ void k_scanBC() {
    __shared__ int sb[128];
    int t = threadIdx.x;
    if (t < 128) sb[t] = (t < SCANB) ? g_bsum[t] : 0;
    __syncthreads();
    #pragma unroll
    for (int off = 1; off < 128; off <<= 1) {
        int v = 0;
        if (t < 128 && t >= off) v = sb[t - off];
        __syncthreads();
        if (t < 128) sb[t] += v;                   // inclusive
        __syncthreads();
    }
    int i = blockIdx.x * blockDim.x + t;
    if (i < NN) {
        int blk = i >> 10;
        g_rowstart[i] += blk ? sb[blk - 1] : 0;
        int d = g_deg[i];
        g_cinv[i] = 1.f / (float)(d > 0 ? d : 1);
        g_fill[i] = 0;
    }
    if (i == 0) g_rowstart[NN] = NE;
}

// counting-sort edges into CSR by destination (reads input edge list directly)
__global__ void k_fill(const void* __restrict__ eiv) {
    int e = blockIdx.x * blockDim.x + threadIdx.x;
    if (e < NE) {
        int s, d;
        if (g_is64) {
            s = (int)((const long long*)eiv)[e];
            d = (int)((const long long*)eiv)[NE + e];
        } else {
            s = ((const int*)eiv)[e];
            d = ((const int*)eiv)[NE + e];
        }
        int pos = g_rowstart[d] + atomicAdd(&g_fill[d], 1);
        g_csr[pos] = s;
    }
}

// ---------------- fused layer kernel part 1 ----------------
// phase0: gather mean rows into transposed smem tile (stride 66: even -> LDS.64 legal)
// pass1: at = ba + meanT@Wa ; restage hT ; pass2: at += hT@Wr ; pass3: as = bl + hT@Wl
// all passes use packed fma.rn.f32x2 (2 IEEE fp32 FMAs per FMA-pipe slot)
// epilogue: hpre = l2n(at) + as ; per-block BN partials
#define SST 66
__global__ void __launch_bounds__(256) k_gemmA(
    const float* __restrict__ x, int layer,
    const float* __restrict__ Wa, const float* __restrict__ Wr,
    const float* __restrict__ Wl,
    const float* __restrict__ ba, const float* __restrict__ bl)
{
    const float* __restrict__ hin = layer ? g_h : x;
    __shared__ __align__(16) float sT[64 * SST];  // input tile transposed [k][n] / stage1
    __shared__ __align__(16) float sW[4096];      // weight [k][c] / stage2
    __shared__ float sRed[8 * 128];               // per-warp stat partials

    int tid = threadIdx.x, warp = tid >> 5, lane = tid & 31;
    int node0 = blockIdx.x * 64;

    // phase0: gather (mean of neighbor h rows) -> sT transposed (2-edge unroll, MLP>=4)
    for (int r = warp * 8; r < warp * 8 + 8; r++) {
        int node = node0 + r;
        float a0 = 0.f, a1 = 0.f;
        if (node < NN) {
            int beg = g_rowstart[node], end = g_rowstart[node + 1];
            float b0 = 0.f, b1 = 0.f;
            int j = beg;
            for (; j + 1 < end; j += 2) {
                const float* r0p = hin + (size_t)g_csr[j] * 64;
                const float* r1p = hin + (size_t)g_csr[j + 1] * 64;
                a0 += r0p[lane];      a1 += r0p[lane + 32];
                b0 += r1p[lane];      b1 += r1p[lane + 32];
            }
            if (j < end) {
                const float* r0p = hin + (size_t)g_csr[j] * 64;
                a0 += r0p[lane];      a1 += r0p[lane + 32];
            }
            float ci = g_cinv[node];
            a0 = (a0 + b0) * ci; a1 = (a1 + b1) * ci;
        }
        sT[lane * SST + r]        = a0;
        sT[(lane + 32) * SST + r] = a1;
    }
    for (int i = tid; i < 1024; i += 256) ((float4*)sW)[i] = ((const float4*)Wa)[i];
    __syncthreads();

    int tx = tid & 15, ty = tid >> 4;
    int c0 = tx * 4, n0 = ty * 4;
    unsigned long long at2[4][2], as2[4][2];
    {
        float4 bb = *(const float4*)(ba + c0);
        #pragma unroll
        for (int i2 = 0; i2 < 4; i2++) {
            at2[i2][0] = pk2(bb.x, bb.y);
            at2[i2][1] = pk2(bb.z, bb.w);
        }
    }

#define GPASS(ACC) \
    _Pragma("unroll 4") \
    for (int k = 0; k < 64; k++) { \
        float2 a01 = *(const float2*)&sT[k*SST + n0]; \
        float2 a23 = *(const float2*)&sT[k*SST + n0 + 2]; \
        unsigned long long p0 = pk2(a01.x, a01.x); \
        unsigned long long p1 = pk2(a01.y, a01.y); \
        unsigned long long p2 = pk2(a23.x, a23.x); \
        unsigned long long p3 = pk2(a23.y, a23.y); \
        ulonglong2 w = *(const ulonglong2*)&sW[k*64 + c0]; \
        fma2(ACC[0][0], p0, w.x); fma2(ACC[0][1], p0, w.y); \
        fma2(ACC[1][0], p1, w.x); fma2(ACC[1][1], p1, w.y); \
        fma2(ACC[2][0], p2, w.x); fma2(ACC[2][1], p2, w.y); \
        fma2(ACC[3][0], p3, w.x); fma2(ACC[3][1], p3, w.y); \
    }

    // pass1: at += meanT @ Wa
    GPASS(at2)
    __syncthreads();

    // restage: sT <- own h rows (transposed), sW <- Wr
    for (int i = tid; i < 1024; i += 256) {
        int n = i >> 4, kc = i & 15;
        int node = node0 + n;
        float4 hv = make_float4(0.f, 0.f, 0.f, 0.f);
        if (node < NN) hv = *(const float4*)(hin + (size_t)node * 64 + kc * 4);
        int kb = kc * 4;
        sT[(kb+0)*SST+n] = hv.x; sT[(kb+1)*SST+n] = hv.y;
        sT[(kb+2)*SST+n] = hv.z; sT[(kb+3)*SST+n] = hv.w;
    }
    __syncthreads();
    for (int i = tid; i < 1024; i += 256) ((float4*)sW)[i] = ((const float4*)Wr)[i];
    __syncthreads();

    // pass2: at += hT @ Wr
    GPASS(at2)
    __syncthreads();
    for (int i = tid; i < 1024; i += 256) ((float4*)sW)[i] = ((const float4*)Wl)[i];
    __syncthreads();

    // pass3: as = bl + hT @ Wl
    {
        float4 bb = *(const float4*)(bl + c0);
        #pragma unroll
        for (int i2 = 0; i2 < 4; i2++) {
            as2[i2][0] = pk2(bb.x, bb.y);
            as2[i2][1] = pk2(bb.z, bb.w);
        }
    }
    GPASS(as2)
    __syncthreads();

    // stage outputs: sT <- at (stride 66), sW <- as (stride 64)
    #pragma unroll
    for (int i2 = 0; i2 < 4; i2++) {
        *(float2*)&sT[(n0+i2)*SST + c0]     = upk2(at2[i2][0]);
        *(float2*)&sT[(n0+i2)*SST + c0 + 2] = upk2(at2[i2][1]);
        *(float2*)&sW[(n0+i2)*64 + c0]      = upk2(as2[i2][0]);
        *(float2*)&sW[(n0+i2)*64 + c0 + 2]  = upk2(as2[i2][1]);
    }
    __syncthreads();

    // epilogue: l2norm + skip-add -> g_hpre ; BN partials
    float cs0 = 0.f, css0 = 0.f, cs1 = 0.f, css1 = 0.f;
    for (int r = warp; r < 64; r += 8) {
        int node = node0 + r;
        float t0 = sT[r*SST + lane], t1 = sT[r*SST + lane + 32];
        float sq = t0*t0 + t1*t1;
        #pragma unroll
        for (int off = 16; off; off >>= 1) sq += __shfl_xor_sync(0xffffffffu, sq, off);
        float inv = 1.f / (sqrtf(sq) + 1e-12f);
        float hp0 = t0 * inv + sW[r*64 + lane];
        float hp1 = t1 * inv + sW[r*64 + lane + 32];
        if (node < NN) {
            g_hpre[(size_t)node*64 + lane]      = hp0;
            g_hpre[(size_t)node*64 + lane + 32] = hp1;
            cs0 += hp0; css0 += hp0*hp0;
            cs1 += hp1; css1 += hp1*hp1;
        }
    }
    sRed[warp*128 + lane]           = cs0;
    sRed[warp*128 + lane + 32]      = cs1;
    sRed[warp*128 + 64 + lane]      = css0;
    sRed[warp*128 + 64 + lane + 32] = css1;
    __syncthreads();
    if (tid < 128) {
        float s = 0.f;
        #pragma unroll
        for (int w = 0; w < 8; w++) s += sRed[w*128 + tid];
        g_part[(size_t)blockIdx.x * 128 + tid] = s;
    }
}

// ---------------- BN finalize: reduce g_part -> g_bn ----------------
__global__ void __launch_bounds__(1024) k_bnfin(
    const float* __restrict__ gamma, const float* __restrict__ beta)
{
    __shared__ float sAcc[1024];
    int tid = threadIdx.x;
    int c = tid & 127, grp = tid >> 7;   // 8 groups
    float s = 0.f;
    for (int b = grp; b < GB; b += 8) s += g_part[(size_t)b * 128 + c];
    sAcc[grp * 128 + c] = s;
    __syncthreads();
    if (tid < 128) {
        float t = 0.f;
        #pragma unroll
        for (int g = 0; g < 8; g++) t += sAcc[g*128 + tid];
        sAcc[tid] = t;
    }
    __syncthreads();
    if (tid < 64) {
        float mu  = sAcc[tid] / (float)NN;
        float var = sAcc[64 + tid] / (float)NN - mu * mu;
        float rs  = 1.f / sqrtf(var + 1e-5f);
        float sc  = rs * gamma[tid];
        g_bn[tid] = sc;
        g_bn[64 + tid] = beta[tid] - mu * sc;
    }
}

// 16-slot butterfly multi-reduce: lane ends with full sum for code CODE(lane)
#define XSTEP(OFF, HALF) { \
    bool hi_ = (lane & OFF) != 0; \
    _Pragma("unroll") \
    for (int i_ = 0; i_ < HALF; i_++) { \
        float send_ = hi_ ? p[i_] : p[i_ + HALF]; \
        float recv_ = __shfl_xor_sync(0xffffffffu, send_, OFF); \
        p[i_] = (hi_ ? p[i_ + HALF] : p[i_]) + recv_; \
    } }
#define REDUCE16() XSTEP(1,8) XSTEP(2,4) XSTEP(4,2) XSTEP(8,1) \
    p[0] += __shfl_xor_sync(0xffffffffu, p[0], 16);

// ---------------- fused: BN apply + relu + xlocal + residual-VQ (+gnn head) --------
__global__ void __launch_bounds__(256) k_nodeB(
    const float* __restrict__ cbl, int layer,
    const float* __restrict__ Wg, const float* __restrict__ bg,
    float* __restrict__ out)
{
    __shared__ float sCb[48 * 65];
    __shared__ float sWg[16 * 65];
    __shared__ float sBn[128];
    __shared__ float sLoss[8];
    int tid = threadIdx.x, warp = tid >> 5, lane = tid & 31;
    if (tid < 128) sBn[tid] = g_bn[tid];
    for (int rid = warp; rid < 48; rid += 8) {
        float v0 = cbl[rid*64 + lane], v1 = cbl[rid*64 + lane + 32];
        float sq = v0*v0 + v1*v1;
        #pragma unroll
        for (int off = 16; off; off >>= 1) sq += __shfl_xor_sync(0xffffffffu, sq, off);
        float inv = 1.f / (sqrtf(sq) + 1e-12f);
        sCb[rid*65 + lane]      = v0 * inv;
        sCb[rid*65 + lane + 32] = v1 * inv;
    }
    for (int i = tid; i < 16*65; i += 256) sWg[i] = 0.f;
    __syncthreads();
    if (layer == 2) {
        for (int i = tid; i < 9*64; i += 256) {
            int j = i / 64, c = i - j*64;
            sWg[j*65 + c] = Wg[c*9 + j];   // transpose [64,9] -> [9,64]
        }
    }
    __syncthreads();

    int mycode = ((lane&1)<<3) | ((lane&2)<<1) | ((lane&4)>>1) | ((lane&8)>>3);
    float lossAcc = 0.f;
    int stride = gridDim.x * 8;
    for (int n = blockIdx.x * 8 + warp; n < NN; n += stride) {
        size_t base = (size_t)n * 64;
        float hp0 = g_hpre[base + lane], hp1 = g_hpre[base + lane + 32];
        float h0 = fmaxf(0.f, fmaf(hp0, sBn[lane],      sBn[64 + lane]));
        float h1 = fmaxf(0.f, fmaf(hp1, sBn[lane + 32], sBn[96 + lane]));
        float xl0 = h0, xl1 = h1;
        if (layer) {
            xl0 += g_xlocal[base + lane];
            xl1 += g_xlocal[base + lane + 32];
        }
        g_xlocal[base + lane] = xl0;
        g_xlocal[base + lane + 32] = xl1;
        if (layer != 2) {                       // layer-2 h is never read again
            g_h[base + lane] = h0;
            g_h[base + lane + 32] = h1;
        }
        float r0 = h0, r1 = h1;
        #pragma unroll
        for (int r = 0; r < 3; r++) {
            float p[16];
            #pragma unroll
            for (int j = 0; j < 16; j++) {
                const float* cb = &sCb[(r*16 + j) * 65];
                p[j] = r0 * cb[lane] + r1 * cb[lane + 32];
            }
            REDUCE16();
            // lanes l and l^16 hold identical (p[0], mycode): 4-step argmax
            float bs = p[0]; int best = mycode;
            #pragma unroll
            for (int off = 8; off; off >>= 1) {
                float os = __shfl_xor_sync(0xffffffffu, bs, off);
                int   oc = __shfl_xor_sync(0xffffffffu, best, off);
                if (os > bs || (os == bs && oc < best)) { bs = os; best = oc; }
            }
            const float* cq = &sCb[(r*16 + best) * 65];
            float q0 = cq[lane], q1 = cq[lane + 32];
            float d0 = q0 - r0, d1 = q1 - r1;
            lossAcc += d0*d0 + d1*d1;
            r0 -= q0; r1 -= q1;
            if (lane == 0) out[IDS_OFF + (size_t)n*9 + layer*3 + r] = (float)best;
        }
        if (layer == 2) {
            float p[16];
            #pragma unroll
            for (int j = 0; j < 16; j++) {
                const float* wrow = &sWg[j * 65];
                p[j] = xl0 * wrow[lane] + xl1 * wrow[lane + 32];
            }
            REDUCE16();
            if (lane < 16 && mycode < 9)
                out[GNN_OFF + (size_t)n*9 + mycode] = p[0] + bg[mycode];
        }
    }
    #pragma unroll
    for (int off = 16; off; off >>= 1) lossAcc += __shfl_xor_sync(0xffffffffu, lossAcc, off);
    if (lane == 0) sLoss[warp] = lossAcc;
    __syncthreads();
    if (tid == 0) {
        float s = 0.f;
        #pragma unroll
        for (int w = 0; w < 8; w++) s += sLoss[w];
        g_cpart[layer * NODEB_BLOCKS + blockIdx.x] = s;
    }
}

// ---------------- pred head: xlocal @ Wp + bp (packed GEMM) + commit write ----------
#define LDT 72
__global__ void __launch_bounds__(256) k_pred(
    const float* __restrict__ Wp, const float* __restrict__ bp,
    float* __restrict__ out)
{
    __shared__ __align__(16) float sW[4096];
    __shared__ __align__(16) float sX[64 * LDT];
    int tid = threadIdx.x;
    int node0 = blockIdx.x * 64;
    for (int i = tid; i < 1024; i += 256) ((float4*)sW)[i] = ((const float4*)Wp)[i];
    for (int i = tid; i < 1024; i += 256) {
        int n = i >> 4, kc = i & 15;
        int node = node0 + n;
        float4 v = make_float4(0.f, 0.f, 0.f, 0.f);
        if (node < NN) v = *(const float4*)(g_xlocal + (size_t)node*64 + kc*4);
        int kb = kc * 4;
        sX[(kb+0)*LDT+n] = v.x; sX[(kb+1)*LDT+n] = v.y;
        sX[(kb+2)*LDT+n] = v.z; sX[(kb+3)*LDT+n] = v.w;
    }
    __syncthreads();
    int tx = tid & 15, ty = tid >> 4, c0 = tx*4, n0 = ty*4;
    unsigned long long acc2[4][2];
    {
        float4 bb = *(const float4*)(bp + c0);
        #pragma unroll
        for (int i2 = 0; i2 < 4; i2++) {
            acc2[i2][0] = pk2(bb.x, bb.y);
            acc2[i2][1] = pk2(bb.z, bb.w);
        }
    }
    #pragma unroll 4
    for (int k = 0; k < 64; k++) {
        float2 a01 = *(const float2*)&sX[k*LDT + n0];
        float2 a23 = *(const float2*)&sX[k*LDT + n0 + 2];
        unsigned long long p0 = pk2(a01.x, a01.x);
        unsigned long long p1 = pk2(a01.y, a01.y);
        unsigned long long p2 = pk2(a23.x, a23.x);
        unsigned long long p3 = pk2(a23.y, a23.y);
        ulonglong2 w = *(const ulonglong2*)&sW[k*64 + c0];
        fma2(acc2[0][0], p0, w.x); fma2(acc2[0][1], p0, w.y);
        fma2(acc2[1][0], p1, w.x); fma2(acc2[1][1], p1, w.y);
        fma2(acc2[2][0], p2, w.x); fma2(acc2[2][1], p2, w.y);
        fma2(acc2[3][0], p3, w.x); fma2(acc2[3][1], p3, w.y);
    }
    #pragma unroll
    for (int i2 = 0; i2 < 4; i2++) {
        int node = node0 + n0 + i2;
        if (node < NN) {
            float2 lo = upk2(acc2[i2][0]);
            float2 hi = upk2(acc2[i2][1]);
            float4 o = make_float4(lo.x, lo.y, hi.x, hi.y);
            *(float4*)(out + (size_t)node*64 + c0) = o;
        }
    }
    if (blockIdx.x == 0) {
        int lane = tid & 31;
        if (tid < 32) {
            float s = 0.f;
            for (int i = lane; i < 3 * NODEB_BLOCKS; i += 32) s += g_cpart[i];
            #pragma unroll
            for (int off = 16; off; off >>= 1) s += __shfl_xor_sync(0xffffffffu, s, off);
            if (lane == 0) out[COMMIT_OFF] = s * (0.25f / (float)(NN * 64));
        }
    }
}

// ---------------- launch ----------------
extern "C" void kernel_launch(void* const* d_in, const int* in_sizes, int n_in,
                              void* d_out, int out_size) {
    const float* x       = (const float*)d_in[0];
    const void*  eiv     = d_in[1];
    const float* Wa      = (const float*)d_in[2];
    const float* ba      = (const float*)d_in[3];
    const float* Wr      = (const float*)d_in[4];
    const float* Wl      = (const float*)d_in[5];
    const float* bl      = (const float*)d_in[6];
    const float* gamma   = (const float*)d_in[7];
    const float* beta    = (const float*)d_in[8];
    const float* cbs     = (const float*)d_in[9];
    const float* Wp      = (const float*)d_in[10];
    const float* bp      = (const float*)d_in[11];
    const float* Wg      = (const float*)d_in[12];
    const float* bg      = (const float*)d_in[13];
    float* out = (float*)d_out;

    k_init<<<(NN + 255)/256, 256>>>((const int*)eiv);
    k_prep<<<(NE + 255)/256, 256>>>(eiv);
    k_scanA<<<SCANB, 1024>>>();
    k_scanBC<<<(NN + 255)/256, 256>>>();
    k_fill<<<(NE + 255)/256, 256>>>(eiv);

    for (int i = 0; i < 3; i++) {
        k_gemmA<<<GB, 256>>>(x, i,
            Wa + i*4096, Wr + i*4096, Wl + i*4096, ba + i*64, bl + i*64);
        k_bnfin<<<1, 1024>>>(gamma + i*64, beta + i*64);
        k_nodeB<<<NODEB_BLOCKS, 256>>>(cbs + i*3*16*64, i, Wg, bg, out);
    }
    k_pred<<<(NN + 63)/64, 256>>>(Wp, bp, out);
}